// round 12
// baseline (speedup 1.0000x reference)
#include <cuda_runtime.h>

// HierarchicalBG: equirect unwrap -> bilinear gather from two (16,H,W) grids
// -> MLP 16->128 (relu) -> 128->3 (softplus).  B = 1048576, out (B,3) f32.
//
// Strategy: per-launch channel-interleave transpose of both grids into
// __device__ scratch ([y][x][16] layout), so each bilinear corner reads
// 64 B contiguous instead of 16 scattered cache lines. Cuts DRAM traffic
// from ~4.7 GB to ~1.5 GB per launch.

#define H0 512
#define W0 1024
#define H1 2048
#define W1 4096

__device__ float g_t0[16u * H0 * W0];   //  33.5 MB interleaved m0
__device__ float g_t1[16u * H1 * W1];   // 537  MB interleaved m1

// ---------------- transpose: [16][HW] -> [HW][16] ----------------
__global__ __launch_bounds__(256)
void transpose_kernel(const float* __restrict__ src, float* __restrict__ dst,
                      int HW) {
    int p = blockIdx.x * blockDim.x + threadIdx.x;
    if (p >= HW) return;
    float v[16];
    #pragma unroll
    for (int r = 0; r < 16; ++r)
        v[r] = __ldg(src + (size_t)r * HW + p);
    float4* d = (float4*)(dst + (size_t)p * 16);
    d[0] = make_float4(v[0],  v[1],  v[2],  v[3]);
    d[1] = make_float4(v[4],  v[5],  v[6],  v[7]);
    d[2] = make_float4(v[8],  v[9],  v[10], v[11]);
    d[3] = make_float4(v[12], v[13], v[14], v[15]);
}

// ------------- gather from interleaved grid, accumulate -------------
static __device__ __forceinline__ void corner_add(const float* __restrict__ g,
                                                  int H, int W,
                                                  int x, int y, float w,
                                                  float* emb) {
    bool valid = (x >= 0) && (x < W) && (y >= 0) && (y < H);
    w = valid ? w : 0.0f;
    int xc = min(max(x, 0), W - 1);
    int yc = min(max(y, 0), H - 1);
    const float4* p = (const float4*)(g + (size_t)(yc * W + xc) * 16);
    #pragma unroll
    for (int k = 0; k < 4; ++k) {
        float4 t = p[k];
        emb[4 * k + 0] = fmaf(w, t.x, emb[4 * k + 0]);
        emb[4 * k + 1] = fmaf(w, t.y, emb[4 * k + 1]);
        emb[4 * k + 2] = fmaf(w, t.z, emb[4 * k + 2]);
        emb[4 * k + 3] = fmaf(w, t.w, emb[4 * k + 3]);
    }
}

static __device__ __forceinline__ void sample_add(const float* __restrict__ g,
                                                  int H, int W,
                                                  float gx, float gy,
                                                  float scale, float* emb) {
    float px = ((gx + 1.0f) * (float)W - 1.0f) * 0.5f;
    float py = ((gy + 1.0f) * (float)H - 1.0f) * 0.5f;
    float x0f = floorf(px), y0f = floorf(py);
    float wx1 = px - x0f, wy1 = py - y0f;
    float wx0 = 1.0f - wx1, wy0 = 1.0f - wy1;
    int x0 = (int)x0f, y0 = (int)y0f;
    corner_add(g, H, W, x0,     y0,     scale * wx0 * wy0, emb);
    corner_add(g, H, W, x0 + 1, y0,     scale * wx1 * wy0, emb);
    corner_add(g, H, W, x0,     y0 + 1, scale * wx0 * wy1, emb);
    corner_add(g, H, W, x0 + 1, y0 + 1, scale * wx1 * wy1, emb);
}

static __device__ __forceinline__ float softplusf(float x) {
    return fmaxf(x, 0.0f) + log1pf(expf(-fabsf(x)));
}

__global__ __launch_bounds__(256, 2)
void hierarchical_bg_kernel(const float* __restrict__ vd,
                            const float* __restrict__ w1,
                            const float* __restrict__ w2,
                            float* __restrict__ out, int n) {
    __shared__ float4 s_w1v[512];   // w1 [16][128] row-major, as float4
    __shared__ float4 s_w2v[96];    // w2 transposed: [3][128], as float4

    {
        float* s1 = (float*)s_w1v;
        float* s2 = (float*)s_w2v;
        for (int t = threadIdx.x; t < 2048; t += blockDim.x) s1[t] = w1[t];
        for (int t = threadIdx.x; t < 384; t += blockDim.x) {
            int i = t >> 7;
            int j = t & 127;
            s2[t] = w2[j * 3 + i];
        }
    }
    __syncthreads();

    int i = blockIdx.x * blockDim.x + threadIdx.x;
    if (i >= n) return;

    // --- unwrap_equirect ---
    float vx = vd[3 * i + 0];
    float vy = vd[3 * i + 1];
    float vz = vd[3 * i + 2];
    float inv = 1.0f / (sqrtf(vx * vx + vy * vy + vz * vz) + 1e-8f);
    float dx = vx * inv, dy = vy * inv, dz = vz * inv;
    const float INV_PI = 0.318309886183790671538f;
    float gx = atan2f(dx, dy) * INV_PI;
    float gy = acosf(fminf(fmaxf(dz, -1.0f), 1.0f)) * (2.0f * INV_PI) - 1.0f;

    // --- gathers from interleaved grids ---
    float emb[16];
    #pragma unroll
    for (int r = 0; r < 16; ++r) emb[r] = 0.0f;
    sample_add(g_t0, H0, W0, gx, gy, 1.0f, emb);
    sample_add(g_t1, H1, W1, gx, gy, 0.5f, emb);

    // --- MLP: h = relu(emb @ w1); out = softplus(h @ w2) ---
    float a0 = 0.0f, a1 = 0.0f, a2 = 0.0f;
    #pragma unroll 4
    for (int g = 0; g < 32; ++g) {
        float hx = 0.0f, hy = 0.0f, hz = 0.0f, hw = 0.0f;
        #pragma unroll
        for (int k = 0; k < 16; ++k) {
            float4 w = s_w1v[k * 32 + g];
            float e = emb[k];
            hx = fmaf(e, w.x, hx);
            hy = fmaf(e, w.y, hy);
            hz = fmaf(e, w.z, hz);
            hw = fmaf(e, w.w, hw);
        }
        hx = fmaxf(hx, 0.0f);
        hy = fmaxf(hy, 0.0f);
        hz = fmaxf(hz, 0.0f);
        hw = fmaxf(hw, 0.0f);
        float4 wa = s_w2v[g];
        float4 wb = s_w2v[32 + g];
        float4 wc = s_w2v[64 + g];
        a0 = fmaf(hx, wa.x, fmaf(hy, wa.y, fmaf(hz, wa.z, fmaf(hw, wa.w, a0))));
        a1 = fmaf(hx, wb.x, fmaf(hy, wb.y, fmaf(hz, wb.z, fmaf(hw, wb.w, a1))));
        a2 = fmaf(hx, wc.x, fmaf(hy, wc.y, fmaf(hz, wc.z, fmaf(hw, wc.w, a2))));
    }

    out[3 * i + 0] = softplusf(a0);
    out[3 * i + 1] = softplusf(a1);
    out[3 * i + 2] = softplusf(a2);
}

extern "C" void kernel_launch(void* const* d_in, const int* in_sizes, int n_in,
                              void* d_out, int out_size) {
    const float* vd = (const float*)d_in[0];   // viewdirs (B,3)
    const float* m0 = (const float*)d_in[1];   // bg_mat0 (1,16,512,1024)
    const float* m1 = (const float*)d_in[2];   // bg_mat1 (1,16,2048,4096)
    const float* w1 = (const float*)d_in[3];   // (16,128)
    const float* w2 = (const float*)d_in[4];   // (128,3)
    float* out = (float*)d_out;

    float* t0;
    float* t1;
    cudaGetSymbolAddress((void**)&t0, g_t0);
    cudaGetSymbolAddress((void**)&t1, g_t1);

    const int HW0 = H0 * W0;
    const int HW1 = H1 * W1;
    transpose_kernel<<<(HW0 + 255) / 256, 256>>>(m0, t0, HW0);
    transpose_kernel<<<(HW1 + 255) / 256, 256>>>(m1, t1, HW1);

    int n = in_sizes[0] / 3;
    const int threads = 256;
    int blocks = (n + threads - 1) / threads;
    hierarchical_bg_kernel<<<blocks, threads>>>(vd, w1, w2, out, n);
}

// round 13
// speedup vs baseline: 1.3805x; 1.3805x over previous
#include <cuda_runtime.h>
#include <cuda_fp16.h>

// HierarchicalBG: equirect unwrap -> bilinear gather from two (16,H,W) grids
// -> MLP 16->128 (relu) -> 128->3 (softplus).  B = 1048576, out (B,3) f32.
//
// Strategy: per-launch channel-interleave transpose of both grids into
// __device__ fp16 scratch ([y][x][16] layout, 32 B/texel). Each bilinear
// corner is then ONE LDG.128. fp16 halves transpose write traffic and
// gather read traffic vs the fp32-interleaved R10 kernel.

#define H0 512
#define W0 1024
#define H1 2048
#define W1 4096

__device__ __half g_t0h[16u * H0 * W0];   //  16.8 MB interleaved m0 (fp16)
__device__ __half g_t1h[16u * H1 * W1];   // 268.4 MB interleaved m1 (fp16)

// ---------------- transpose: [16][HW] fp32 -> [HW][16] fp16 ----------------
__global__ __launch_bounds__(256)
void transpose_kernel(const float* __restrict__ src, __half* __restrict__ dst,
                      int HW) {
    int p = blockIdx.x * blockDim.x + threadIdx.x;
    if (p >= HW) return;
    float v[16];
    #pragma unroll
    for (int r = 0; r < 16; ++r)
        v[r] = __ldg(src + (size_t)r * HW + p);
    __half2 h[8];
    #pragma unroll
    for (int k = 0; k < 8; ++k)
        h[k] = __floats2half2_rn(v[2 * k], v[2 * k + 1]);
    uint4* d = (uint4*)(dst + (size_t)p * 16);
    const uint4* hs = (const uint4*)h;
    d[0] = hs[0];
    d[1] = hs[1];
}

// ------------- gather one corner (16 fp16 ch = one LDG.128) -------------
static __device__ __forceinline__ void corner_add(const __half* __restrict__ g,
                                                  int H, int W,
                                                  int x, int y, float w,
                                                  float* emb) {
    bool valid = (x >= 0) && (x < W) && (y >= 0) && (y < H);
    w = valid ? w : 0.0f;
    int xc = min(max(x, 0), W - 1);
    int yc = min(max(y, 0), H - 1);
    const uint4* p = (const uint4*)(g + (size_t)(yc * W + xc) * 16);
    uint4 a = p[0];
    uint4 b = p[1];
    const __half2* ha = (const __half2*)&a;
    const __half2* hb = (const __half2*)&b;
    #pragma unroll
    for (int k = 0; k < 4; ++k) {
        float2 f = __half22float2(ha[k]);
        emb[2 * k + 0] = fmaf(w, f.x, emb[2 * k + 0]);
        emb[2 * k + 1] = fmaf(w, f.y, emb[2 * k + 1]);
    }
    #pragma unroll
    for (int k = 0; k < 4; ++k) {
        float2 f = __half22float2(hb[k]);
        emb[8 + 2 * k + 0] = fmaf(w, f.x, emb[8 + 2 * k + 0]);
        emb[8 + 2 * k + 1] = fmaf(w, f.y, emb[8 + 2 * k + 1]);
    }
}

static __device__ __forceinline__ void sample_add(const __half* __restrict__ g,
                                                  int H, int W,
                                                  float gx, float gy,
                                                  float scale, float* emb) {
    float px = ((gx + 1.0f) * (float)W - 1.0f) * 0.5f;
    float py = ((gy + 1.0f) * (float)H - 1.0f) * 0.5f;
    float x0f = floorf(px), y0f = floorf(py);
    float wx1 = px - x0f, wy1 = py - y0f;
    float wx0 = 1.0f - wx1, wy0 = 1.0f - wy1;
    int x0 = (int)x0f, y0 = (int)y0f;
    corner_add(g, H, W, x0,     y0,     scale * wx0 * wy0, emb);
    corner_add(g, H, W, x0 + 1, y0,     scale * wx1 * wy0, emb);
    corner_add(g, H, W, x0,     y0 + 1, scale * wx0 * wy1, emb);
    corner_add(g, H, W, x0 + 1, y0 + 1, scale * wx1 * wy1, emb);
}

static __device__ __forceinline__ float softplusf(float x) {
    return fmaxf(x, 0.0f) + log1pf(expf(-fabsf(x)));
}

__global__ __launch_bounds__(256, 3)
void hierarchical_bg_kernel(const float* __restrict__ vd,
                            const float* __restrict__ w1,
                            const float* __restrict__ w2,
                            float* __restrict__ out, int n) {
    __shared__ float4 s_w1v[512];   // w1 [16][128] row-major, as float4
    __shared__ float4 s_w2v[96];    // w2 transposed: [3][128], as float4

    {
        float* s1 = (float*)s_w1v;
        float* s2 = (float*)s_w2v;
        for (int t = threadIdx.x; t < 2048; t += blockDim.x) s1[t] = w1[t];
        for (int t = threadIdx.x; t < 384; t += blockDim.x) {
            int i = t >> 7;
            int j = t & 127;
            s2[t] = w2[j * 3 + i];
        }
    }
    __syncthreads();

    int i = blockIdx.x * blockDim.x + threadIdx.x;
    if (i >= n) return;

    // --- unwrap_equirect ---
    float vx = vd[3 * i + 0];
    float vy = vd[3 * i + 1];
    float vz = vd[3 * i + 2];
    float inv = 1.0f / (sqrtf(vx * vx + vy * vy + vz * vz) + 1e-8f);
    float dx = vx * inv, dy = vy * inv, dz = vz * inv;
    const float INV_PI = 0.318309886183790671538f;
    float gx = atan2f(dx, dy) * INV_PI;
    float gy = acosf(fminf(fmaxf(dz, -1.0f), 1.0f)) * (2.0f * INV_PI) - 1.0f;

    // --- gathers from fp16-interleaved grids ---
    float emb[16];
    #pragma unroll
    for (int r = 0; r < 16; ++r) emb[r] = 0.0f;
    sample_add(g_t0h, H0, W0, gx, gy, 1.0f, emb);
    sample_add(g_t1h, H1, W1, gx, gy, 0.5f, emb);

    // --- MLP: h = relu(emb @ w1); out = softplus(h @ w2) ---
    float a0 = 0.0f, a1 = 0.0f, a2 = 0.0f;
    #pragma unroll 4
    for (int g = 0; g < 32; ++g) {
        float hx = 0.0f, hy = 0.0f, hz = 0.0f, hw = 0.0f;
        #pragma unroll
        for (int k = 0; k < 16; ++k) {
            float4 w = s_w1v[k * 32 + g];
            float e = emb[k];
            hx = fmaf(e, w.x, hx);
            hy = fmaf(e, w.y, hy);
            hz = fmaf(e, w.z, hz);
            hw = fmaf(e, w.w, hw);
        }
        hx = fmaxf(hx, 0.0f);
        hy = fmaxf(hy, 0.0f);
        hz = fmaxf(hz, 0.0f);
        hw = fmaxf(hw, 0.0f);
        float4 wa = s_w2v[g];
        float4 wb = s_w2v[32 + g];
        float4 wc = s_w2v[64 + g];
        a0 = fmaf(hx, wa.x, fmaf(hy, wa.y, fmaf(hz, wa.z, fmaf(hw, wa.w, a0))));
        a1 = fmaf(hx, wb.x, fmaf(hy, wb.y, fmaf(hz, wb.z, fmaf(hw, wb.w, a1))));
        a2 = fmaf(hx, wc.x, fmaf(hy, wc.y, fmaf(hz, wc.z, fmaf(hw, wc.w, a2))));
    }

    out[3 * i + 0] = softplusf(a0);
    out[3 * i + 1] = softplusf(a1);
    out[3 * i + 2] = softplusf(a2);
}

extern "C" void kernel_launch(void* const* d_in, const int* in_sizes, int n_in,
                              void* d_out, int out_size) {
    const float* vd = (const float*)d_in[0];   // viewdirs (B,3)
    const float* m0 = (const float*)d_in[1];   // bg_mat0 (1,16,512,1024)
    const float* m1 = (const float*)d_in[2];   // bg_mat1 (1,16,2048,4096)
    const float* w1 = (const float*)d_in[3];   // (16,128)
    const float* w2 = (const float*)d_in[4];   // (128,3)
    float* out = (float*)d_out;

    __half* t0;
    __half* t1;
    cudaGetSymbolAddress((void**)&t0, g_t0h);
    cudaGetSymbolAddress((void**)&t1, g_t1h);

    const int HW0 = H0 * W0;
    const int HW1 = H1 * W1;
    transpose_kernel<<<(HW0 + 255) / 256, 256>>>(m0, t0, HW0);
    transpose_kernel<<<(HW1 + 255) / 256, 256>>>(m1, t1, HW1);

    int n = in_sizes[0] / 3;
    const int threads = 256;
    int blocks = (n + threads - 1) / threads;
    hierarchical_bg_kernel<<<blocks, threads>>>(vd, w1, w2, out, n);
}